// round 15
// baseline (speedup 1.0000x reference)
#include <cuda_runtime.h>
#include <cuda_bf16.h>
#include <cuda_fp16.h>
#include <cstdint>

#define T_LEN 2048
#define KP    17
#define KPAD  18
#define HID   64
#define B_SZ  32
#define NCLS  10
#define TILE_T 16
#define NT    (T_LEN / TILE_T)
#define RPB   (T_LEN * KP)            // 34816 rows per batch
#define TILES_PB (RPB / 128)          // 272
#define NTILES (TILES_PB * B_SZ)      // 8704
#define PAD   64
#define PADROWS (RPB + 2*PAD)
#define KWPAD 100
#define HDR   4096
#define SBH_BYTES (64*KWPAD*4)        // 25600
#define SMEM_MMA (HDR + SBH_BYTES)    // 29696
#define YW2   33                      // ysm word stride (half2 words per row)

typedef unsigned long long ull;

__device__ uint32_t g_y0h[(size_t)B_SZ * RPB * 32];       // fp16 y0 (residual stream)
__device__ float    g_buf1[(size_t)B_SZ * RPB * HID];
__device__ uint32_t g_xa0[(size_t)B_SZ * PADROWS * 32];   // fp16 premixed layer-1 A
__device__ uint32_t g_xa1[(size_t)B_SZ * PADROWS * 32];   // fp16 premixed layer-2 A
__device__ float    g_Wf[3][3 * HID * HID];
__device__ unsigned short g_Wh[2][64 * 192];   // fp16 weights
__device__ float    g_beta[3][HID];
__device__ int      g_nnz[KP];
__device__ int      g_vidx[KP][KP];   // zero-padded to 4 entries
__device__ float    g_vw[KP][KP];
__device__ float    g_part[(size_t)NTILES * 64];
__device__ float    g_part1[(size_t)NTILES * 64];

// word position within a row for channel-pair c2 (LDG.128-friendly layout):
__device__ __forceinline__ int wpos(int c2) {
    return ((c2 & 3) << 3) | ((c2 >> 3) << 1) | ((c2 >> 2) & 1);
}
// c2 for pair-index p in 0..15 such that (c2, c2+4) -> (wpos, wpos+1)
__device__ __forceinline__ int c2base(int p) {
    return (p & 3) | ((p >> 2) << 3);
}

// ---------------- helpers ---------------------------------------------------
__device__ __forceinline__ void fma2(ull& d, ull a, ull b) {
    asm("fma.rn.f32x2 %0, %1, %2, %3;" : "=l"(d) : "l"(a), "l"(b), "l"(d));
}
__device__ __forceinline__ ull pack2(float x, float y) {
    ull r; asm("mov.b64 %0, {%1, %2};" : "=l"(r) : "f"(x), "f"(y)); return r;
}
__device__ __forceinline__ float2 unpack2(ull v) {
    float2 r; asm("mov.b64 {%0, %1}, %2;" : "=f"(r.x), "=f"(r.y) : "l"(v)); return r;
}
__device__ __forceinline__ uint32_t f16pack(float x, float y) {   // x -> low half
    uint32_t r;
    asm("cvt.rn.f16x2.f32 %0, %1, %2;" : "=r"(r) : "f"(y), "f"(x));
    return r;
}
__device__ __forceinline__ __half2 u2h2(uint32_t v) {
    return *reinterpret_cast<__half2*>(&v);
}
__device__ __forceinline__ uint32_t h22u(__half2 h) {
    return *reinterpret_cast<uint32_t*>(&h);
}
__device__ __forceinline__ uint32_t s2u(const void* p) {
    uint32_t a;
    asm("{ .reg .u64 t; cvta.to.shared.u64 t, %1; cvt.u32.u64 %0, t; }" : "=r"(a) : "l"(p));
    return a;
}
__device__ __forceinline__ void ldm4(uint32_t* r, uint32_t addr) {
    asm volatile("ldmatrix.sync.aligned.m8n8.x4.shared.b16 {%0,%1,%2,%3}, [%4];"
        : "=r"(r[0]), "=r"(r[1]), "=r"(r[2]), "=r"(r[3]) : "r"(addr));
}
__device__ __forceinline__ void mma_f16(float* d, const uint32_t* a, uint32_t b0, uint32_t b1) {
    asm volatile("mma.sync.aligned.m16n8k16.row.col.f32.f16.f16.f32 "
        "{%0,%1,%2,%3}, {%4,%5,%6,%7}, {%8,%9}, {%0,%1,%2,%3};"
        : "+f"(d[0]), "+f"(d[1]), "+f"(d[2]), "+f"(d[3])
        : "r"(a[0]), "r"(a[1]), "r"(a[2]), "r"(a[3]), "r"(b0), "r"(b1));
}

// ---------------------------------------------------------------------------
// prep: BN-folded fused weights; fp16 weights (layers 1,2); CSR adj
// ---------------------------------------------------------------------------
__global__ void prep_kernel(const float* __restrict__ adj,
                            const float* __restrict__ gw0, const float* __restrict__ gw1,
                            const float* __restrict__ gw2, const float* __restrict__ tcn,
                            const float* __restrict__ bs, const float* __restrict__ bb,
                            const float* __restrict__ bm, const float* __restrict__ bv)
{
    int blk = blockIdx.x, tau = blockIdx.y, o = threadIdx.x;
    const float* gw = (blk == 0) ? gw0 : ((blk == 1) ? gw1 : gw2);
    int CIN = (blk == 0) ? 3 : 64;
    float rstd = rsqrtf(bv[blk*64 + o] + 1e-5f);
    float inv  = bs[blk*64 + o] * rstd;
    if (tau == 0)
        g_beta[blk][o] = bb[blk*64 + o] - bs[blk*64 + o] * bm[blk*64 + o] * rstd;
    if (blk == 0 && tau == 0 && o < KP) {
        int n = 0;
        for (int v = 0; v < KP; v++) {
            float w = adj[v*KP + o];
            if (w != 0.f) { g_vidx[o][n] = v; g_vw[o][n] = w; n++; }
        }
        for (int i = n; i < 4; i++) { g_vidx[o][i] = 0; g_vw[o][i] = 0.f; }
        g_nnz[o] = n;
    }
    const float* tw = tcn + (size_t)blk * HID * HID * 3;
    for (int j = 0; j < CIN; j++) {
        float s = 0.f;
        for (int i = 0; i < HID; i++)
            s += gw[j*HID + i] * tw[(o*HID + i)*3 + tau];
        float val = s * inv;
        g_Wf[blk][(tau*CIN + j)*HID + o] = val;
        if (blk >= 1) {
            __half h = __float2half(val);
            g_Wh[blk-1][o*192 + tau*64 + j] = reinterpret_cast<unsigned short&>(h);
        }
    }
}

// ---------------------------------------------------------------------------
// zero pad rows of g_xa0 / g_xa1
// ---------------------------------------------------------------------------
__global__ void zero_pads()
{
    int b = blockIdx.x;
    int u = blockIdx.y * 256 + threadIdx.x;
    int o = u >> 5, w = u & 31;
    size_t pr = (size_t)b*PADROWS + (o < PAD ? o : (size_t)(PAD + RPB + (o - PAD)));
    g_xa0[pr*32 + w] = 0u;
    g_xa1[pr*32 + w] = 0u;
}

// ---------------------------------------------------------------------------
// cleanup premix: t-groups straddling a 128-row tile boundary (layer-2 input)
// ---------------------------------------------------------------------------
__global__ __launch_bounds__(288)
void clean_premix(const float* __restrict__ y)
{
    int k = blockIdx.x + 1;           // boundary index within batch, 1..271
    if (k % 17 == 0) return;
    int b = blockIdx.y;
    int g = (k * 128) / 17;           // straddling group
    int tid = threadIdx.x;
    const float* ybase = y + ((size_t)b*RPB + (size_t)g*17)*64;
    for (int u = tid; u < 17*16; u += 288) {
        int kk = u >> 4, p = u & 15;
        int c2 = c2base(p);
        ull accA = 0ull, accB = 0ull;
        #pragma unroll
        for (int i = 0; i < 4; i++) {
            float wv = g_vw[kk][i];
            ull wd = pack2(wv, wv);
            const float* yr = ybase + g_vidx[kk][i]*64 + 2*c2;
            fma2(accA, wd, *(const ull*)yr);
            fma2(accB, wd, *(const ull*)(yr + 8));
        }
        float2 a = unpack2(accA), c = unpack2(accB);
        size_t pr = (size_t)b*PADROWS + PAD + (size_t)g*17 + kk;
        int pos = wpos(c2);
        *(uint2*)(g_xa1 + pr*32 + pos) = make_uint2(f16pack(a.x, a.y), f16pack(c.x, c.y));
    }
}

// ---------------------------------------------------------------------------
// mma.sync GEMM layer: single-pass fp16 (A fp16 premixed, B fp16 in smem,
// fp32 accum). 1 tile/CTA; A loaded per ks-half (small reg footprint),
// 32-bit addressing throughout.
// FUSE (layer1): residual read from fp16 y0h; premix layer-2 input in-smem
//   (fp16 half2 math) -> g_xa1; y1 written (fp32) only for boundary rows;
//   pool y1 -> g_part1.
// POOL (layer2): pool relu(z+beta) -> g_part.
// ---------------------------------------------------------------------------
template<int SH, bool POOL, bool FUSE>
__global__ __launch_bounds__(128, 5)
void mma_kernel(const uint32_t* __restrict__ xres, float* __restrict__ yout,
                const uint32_t* __restrict__ xa, uint32_t* __restrict__ xaout,
                int wsel, int blk)
{
    extern __shared__ char smem[];
    // header [0, HDR): sbias(64f) pw(256f) svwh(289u) svix(289i)
    float*    sbias = (float*)smem;
    float*    pw    = sbias + 64;
    uint32_t* svwh  = (uint32_t*)(pw + 256);
    int*      svix  = (int*)(svwh + 289);
    // B region at HDR; ysm (fp16x2 words) reuses it post-mainloop
    uint32_t* sBh   = (uint32_t*)(smem + HDR);
    uint32_t* ysmw  = (uint32_t*)(smem + HDR);

    const int tid  = threadIdx.x;
    const int w    = tid >> 5;
    const int lane = tid & 31;
    const int grp  = lane >> 2;
    const int thr  = lane & 3;

    {
        const uint4* wh4 = (const uint4*)g_Wh[wsel];
        for (int u = tid; u < 64*24; u += 128) {
            int n = u / 24, q = u - n*24;
            *(uint4*)((char*)sBh + n*KWPAD*4 + q*16) = wh4[u];
        }
        if (tid < 64) sbias[tid] = g_beta[blk][tid];
        if (FUSE) {
            for (int u = tid; u < 289; u += 128) {
                float wv = ((const float*)g_vw)[u];
                svwh[u] = f16pack(wv, wv);
                svix[u] = ((const int*)g_vidx)[u];
            }
        }
    }
    __syncthreads();

    const uint32_t sb = s2u(smem);
    const int rowsel = (lane & 7) + ((lane >> 4) << 3);
    const int kq     = ((lane >> 3) & 1) * 4;
    const uint32_t bAH = sb + HDR + (uint32_t)(rowsel*KWPAD + kq)*4;

    const int tile = blockIdx.x;
    const int b    = tile / TILES_PB;
    const int r0b  = (tile - b*TILES_PB)*128;      // batch-local tile row base
    const int rloc = r0b + w*32 + grp;
    const uint32_t prow0 = (uint32_t)b*PADROWS + PAD + rloc;

    float C[2][8][4];
    #pragma unroll
    for (int mi = 0; mi < 2; mi++)
        #pragma unroll
        for (int nf = 0; nf < 8; nf++)
            #pragma unroll
            for (int q = 0; q < 4; q++) C[mi][nf][q] = 0.f;

    #pragma unroll
    for (int ti = 0; ti < 3; ti++) {
        const uint32_t base = (prow0 + (ti - 1)*SH)*32 + thr*8;
        #pragma unroll
        for (int ks = 0; ks < 4; ks++) {
            uint4 Hk[2][2];      // [mi][row0/row8] loaded per ks-half
            if ((ks & 1) == 0) {
                #pragma unroll
                for (int mi = 0; mi < 2; mi++) {
                    Hk[mi][0] = *(const uint4*)(xa + base + mi*512 + (ks>>1)*4);
                    Hk[mi][1] = *(const uint4*)(xa + base + mi*512 + 256 + (ks>>1)*4);
                }
            }
            const int kstep = ti*4 + ks;
            #pragma unroll
            for (int p = 0; p < 4; p++) {
                uint32_t bh[4];
                ldm4(bh, bAH + (uint32_t)(p*16*KWPAD*4 + kstep*32));
                #pragma unroll
                for (int mi = 0; mi < 2; mi++) {
                    uint32_t ah[4];
                    if ((ks & 1) == 0) {
                        ah[0]=Hk[mi][0].x; ah[2]=Hk[mi][0].y;
                        ah[1]=Hk[mi][1].x; ah[3]=Hk[mi][1].y;
                    } else {
                        ah[0]=Hk[mi][0].z; ah[2]=Hk[mi][0].w;
                        ah[1]=Hk[mi][1].z; ah[3]=Hk[mi][1].w;
                    }
                    mma_f16(C[mi][2*p],   ah, bh[0], bh[1]);
                    mma_f16(C[mi][2*p+1], ah, bh[2], bh[3]);
                }
            }
        }
    }

    if (FUSE) __syncthreads();    // B reads complete; ysm may overwrite B

    const int gstart = (r0b + 16) / 17;
    const int glast  = (r0b + 111) / 17;

    // ---- epilogue ----
    const uint32_t grow_base = (uint32_t)tile*128 + w*32 + grp;
    float csum[16];
    #pragma unroll
    for (int u = 0; u < 16; u++) csum[u] = 0.f;

    #pragma unroll
    for (int mi = 0; mi < 2; mi++) {
        #pragma unroll
        for (int h = 0; h < 2; h++) {
            uint32_t gr = grow_base + mi*16 + h*8;
            const int lrow = w*32 + grp + mi*16 + h*8;
            bool wr = true;
            if (FUSE) {
                int gidx = (r0b + lrow) / 17;
                wr = (gidx < gstart) || (gidx > glast);
            }
            const uint32_t* xr = xres + (size_t)gr*32;
            #pragma unroll
            for (int nf = 0; nf < 8; nf++) {
                int c2i = nf*4 + thr;
                float2 bsv = *(const float2*)(sbias + c2i*2);
                float o0 = fmaxf(C[mi][nf][2*h]   + bsv.x, 0.f);
                float o1 = fmaxf(C[mi][nf][2*h+1] + bsv.y, 0.f);
                if (!POOL) {
                    float2 xv = __half22float2(u2h2(xr[c2i]));   // fp16 residual
                    o0 += xv.x; o1 += xv.y;
                    if (!FUSE || wr) {
                        float2* yr = (float2*)(yout + (size_t)gr*64);
                        yr[c2i] = make_float2(o0, o1);
                    }
                    if (FUSE)
                        ysmw[lrow*YW2 + c2i] = f16pack(o0, o1);
                }
                csum[2*nf]   += o0;
                csum[2*nf+1] += o1;
            }
        }
    }
    if (POOL || FUSE) {
        #pragma unroll
        for (int u = 0; u < 16; u++) {
            csum[u] += __shfl_xor_sync(0xffffffffu, csum[u], 4);
            csum[u] += __shfl_xor_sync(0xffffffffu, csum[u], 8);
            csum[u] += __shfl_xor_sync(0xffffffffu, csum[u], 16);
        }
        if (grp == 0) {
            #pragma unroll
            for (int nf = 0; nf < 8; nf++) {
                pw[w*64 + nf*8 + thr*2]     = csum[2*nf];
                pw[w*64 + nf*8 + thr*2 + 1] = csum[2*nf+1];
            }
        }
        __syncthreads();                      // also orders ysm for premix
        if (tid < 64) {
            float v = pw[tid] + pw[64 + tid] + pw[128 + tid] + pw[192 + tid];
            if (POOL) g_part[(size_t)tile*64 + tid] = v;
            else      g_part1[(size_t)tile*64 + tid] = v;
        }
    }

    if (FUSE) {
        const int nitems = (glast - gstart + 1) * (17*16);
        const uint32_t bnk = (uint32_t)b*PADROWS + PAD;
        for (int u = tid; u < nitems; u += 128) {
            int rig = u >> 4, p = u & 15;
            int c2 = c2base(p);
            int gq  = rig / 17;
            int kk  = rig - gq*17;
            int g   = gstart + gq;
            int gr  = g*17 + kk;                 // row within batch
            const int lbase = g*17 - r0b;
            __half2 accA = __float2half2_rn(0.f);
            __half2 accB = __float2half2_rn(0.f);
            #pragma unroll
            for (int i = 0; i < 4; i++) {
                __half2 wd = u2h2(svwh[kk*17 + i]);
                const uint32_t* yr = ysmw + (lbase + svix[kk*17 + i])*YW2;
                accA = __hfma2(u2h2(yr[c2]),     wd, accA);
                accB = __hfma2(u2h2(yr[c2 + 4]), wd, accB);
            }
            uint32_t pr = bnk + gr;
            int pos = wpos(c2);
            *(uint2*)(xaout + (size_t)pr*32 + pos) = make_uint2(h22u(accA), h22u(accB));
        }
    }
}

// ---------------------------------------------------------------------------
// Layer 0 (CIN=3) fp32 f32x2 kernel + FUSED premix of layer-1 input (fp16);
// y0 stored as fp16 half2 words (residual stream for layer 1).
// ---------------------------------------------------------------------------
#define YW 68
__global__ __launch_bounds__(288, 2)
void stblock0(const float* __restrict__ xin, uint32_t* __restrict__ youth,
              const float* __restrict__ adjg)
{
    constexpr int CIN = 3, D = 1;
    constexpr int NTT  = TILE_T + 2*D;
    constexpr int XW   = NTT*KPAD + 2;
    constexpr int XS   = ((CIN*XW + 3) & ~3);
    constexpr int WS_SZ = 3*CIN*HID;
    constexpr int YSM  = 272*YW;

    extern __shared__ float sm[];
    float* ysm  = sm;
    float* xg   = sm + YSM;
    float* Ws   = xg + XS;
    float* sadj = Ws + WS_SZ;
    float* sbet = sadj + 308;
    float* svw  = sbet + 64;
    int*   svix = (int*)(svw + 289);

    const int tid = threadIdx.x;
    const int b   = blockIdx.y;
    const int t0  = blockIdx.x * TILE_T;

    for (int u = tid; u < KP*KPAD; u += 288) {
        int v = u / KPAD, k = u - v*KPAD;
        sadj[u] = (k < KP) ? adjg[v*KP + k] : 0.f;
    }
    if (tid < HID) sbet[tid] = g_beta[0][tid];
    for (int u = tid; u < WS_SZ; u += 288) Ws[u] = g_Wf[0][u];
    for (int u = tid; u < 289; u += 288) {
        svw[u]  = ((const float*)g_vw)[u];
        svix[u] = ((const int*)g_vidx)[u];
    }
    __syncthreads();

    const float* xb = xin + (size_t)b * T_LEN * KP * CIN;
    for (int u = tid; u < NTT * CIN; u += 288) {
        int tl = u / CIN, c = u - tl*CIN;
        int tg = t0 + tl - D;
        float raw[KP];
        if (tg >= 0 && tg < T_LEN) {
            const float* xr = xb + (size_t)tg * KP * CIN + c;
            #pragma unroll
            for (int v = 0; v < KP; v++) raw[v] = __ldg(xr + v*CIN);
        } else {
            #pragma unroll
            for (int v = 0; v < KP; v++) raw[v] = 0.f;
        }
        ull s2[KPAD/2];
        #pragma unroll
        for (int p = 0; p < KPAD/2; p++) s2[p] = 0ull;
        #pragma unroll
        for (int v = 0; v < KP; v++) {
            ull rd = pack2(raw[v], raw[v]);
            const ull* ap = (const ull*)(sadj + v*KPAD);
            #pragma unroll
            for (int p = 0; p < KPAD/2; p++) fma2(s2[p], rd, ap[p]);
        }
        ull* xo = (ull*)(xg + c*XW + tl*KPAD);
        #pragma unroll
        for (int p = 0; p < KPAD/2; p++) xo[p] = s2[p];
    }
    __syncthreads();

    const int cg = tid & 7;
    const int rg = tid >> 3;
    const int r0 = rg * 8;

    ull acc[4][8];
    #pragma unroll
    for (int q = 0; q < 4; q++)
        #pragma unroll
        for (int p = 0; p < 8; p++) acc[q][p] = 0ull;

    #pragma unroll
    for (int tau = 0; tau < 3; tau++) {
        const float* wsrc = Ws + tau*CIN*HID;
        const float* xpb = xg + tau*(KPAD*D) + r0;
        #pragma unroll
        for (int j = 0; j < CIN; j++) {
            const ull* xp = (const ull*)(xpb + j*XW);
            ull x0 = xp[0], x1 = xp[1], x2 = xp[2], x3 = xp[3];
            const float* wr = wsrc + j*HID + cg*8;
            float4 wa = *(const float4*)(wr);
            float4 wb = *(const float4*)(wr + 4);
            ull wd[8];
            wd[0] = pack2(wa.x, wa.x); wd[1] = pack2(wa.y, wa.y);
            wd[2] = pack2(wa.z, wa.z); wd[3] = pack2(wa.w, wa.w);
            wd[4] = pack2(wb.x, wb.x); wd[5] = pack2(wb.y, wb.y);
            wd[6] = pack2(wb.z, wb.z); wd[7] = pack2(wb.w, wb.w);
            #pragma unroll
            for (int p = 0; p < 8; p++) {
                fma2(acc[0][p], x0, wd[p]);
                fma2(acc[1][p], x1, wd[p]);
                fma2(acc[2][p], x2, wd[p]);
                fma2(acc[3][p], x3, wd[p]);
            }
        }
    }

    const float4 bA = *(const float4*)(sbet + cg*8);
    const float4 bB = *(const float4*)(sbet + cg*8 + 4);
    #pragma unroll
    for (int q = 0; q < 4; q++) {
        float vr[2][8];
        #pragma unroll
        for (int p = 0; p < 8; p++) {
            float2 u2 = unpack2(acc[q][p]);
            vr[0][p] = u2.x; vr[1][p] = u2.y;
        }
        #pragma unroll
        for (int h = 0; h < 2; h++) {
            int r  = r0 + 2*q + h;
            int tl = r / KPAD;
            int kk = r - tl*KPAD;
            if (kk < KP) {
                size_t grow = ((size_t)b*T_LEN + (t0 + tl))*KP + kk;
                float o[8];
                o[0] = fmaxf(vr[h][0] + bA.x, 0.f);
                o[1] = fmaxf(vr[h][1] + bA.y, 0.f);
                o[2] = fmaxf(vr[h][2] + bA.z, 0.f);
                o[3] = fmaxf(vr[h][3] + bA.w, 0.f);
                o[4] = fmaxf(vr[h][4] + bB.x, 0.f);
                o[5] = fmaxf(vr[h][5] + bB.y, 0.f);
                o[6] = fmaxf(vr[h][6] + bB.z, 0.f);
                o[7] = fmaxf(vr[h][7] + bB.w, 0.f);
                uint4 hv;
                hv.x = f16pack(o[0], o[1]); hv.y = f16pack(o[2], o[3]);
                hv.z = f16pack(o[4], o[5]); hv.w = f16pack(o[6], o[7]);
                *(uint4*)(youth + grow*32 + cg*4) = hv;
                int yr = tl*KP + kk;
                *(float4*)(ysm + yr*YW + cg*8)     = make_float4(o[0], o[1], o[2], o[3]);
                *(float4*)(ysm + yr*YW + cg*8 + 4) = make_float4(o[4], o[5], o[6], o[7]);
            }
        }
    }
    __syncthreads();

    // ---- fused premix: layer-1 A = adj * y0 (packed, fixed-4 unroll, fp16) ----
    const size_t bnk = ((size_t)b*PADROWS + PAD + (size_t)t0*KP);
    for (int u = tid; u < 272*16; u += 288) {
        int row = u >> 4, p = u & 15;
        int c2 = c2base(p);
        int tl = row / KP, kk = row - tl*KP;
        const float* yb = ysm + tl*KP*YW + 2*c2;
        ull accA = 0ull, accB = 0ull;
        #pragma unroll
        for (int i = 0; i < 4; i++) {
            float wv = svw[kk*17 + i];
            ull wd = pack2(wv, wv);
            const float* yr = yb + svix[kk*17 + i]*YW;
            fma2(accA, wd, *(const ull*)yr);
            fma2(accB, wd, *(const ull*)(yr + 8));
        }
        float2 a = unpack2(accA), c = unpack2(accB);
        size_t pr = bnk + row;
        int pos = wpos(c2);
        *(uint2*)(g_xa0 + pr*32 + pos) = make_uint2(f16pack(a.x, a.y), f16pack(c.x, c.y));
    }
}

// ---------------------------------------------------------------------------
// finalize: pool = Σ(g_part + g_part1) -> LayerNorm -> FC
// ---------------------------------------------------------------------------
__global__ void finalize_kernel(const float* __restrict__ lns, const float* __restrict__ lnb,
                                const float* __restrict__ fcw, const float* __restrict__ fcb,
                                float* __restrict__ out)
{
    int b = blockIdx.x;
    int c = threadIdx.x;
    float s = 0.f;
    const float* pp = g_part  + (size_t)b * TILES_PB * 64;
    const float* pq = g_part1 + (size_t)b * TILES_PB * 64;
    for (int t = 0; t < TILES_PB; t++) s += pp[t*64 + c] + pq[t*64 + c];
    s *= (1.f / ((float)T_LEN * (float)KP));

    __shared__ float red[64];
    __shared__ float sf[64];
    red[c] = s; __syncthreads();
    for (int off = 32; off; off >>= 1) { if (c < off) red[c] += red[c+off]; __syncthreads(); }
    float mu = red[0] * (1.f/64.f);
    __syncthreads();
    float d = s - mu;
    red[c] = d * d; __syncthreads();
    for (int off = 32; off; off >>= 1) { if (c < off) red[c] += red[c+off]; __syncthreads(); }
    float var = red[0] * (1.f/64.f);
    float f = d * rsqrtf(var + 1e-5f) * lns[c] + lnb[c];
    sf[c] = f; __syncthreads();
    if (c < NCLS) {
        float o = fcb[c];
        #pragma unroll
        for (int i = 0; i < 64; i++) o += sf[i] * fcw[i*NCLS + c];
        out[b*NCLS + c] = o;
    }
}

extern "C" void kernel_launch(void* const* d_in, const int* in_sizes, int n_in,
                              void* d_out, int out_size)
{
    const float* kpts = (const float*)d_in[0];
    const float* adj  = (const float*)d_in[1];
    const float* gw0  = (const float*)d_in[2];
    const float* gw1  = (const float*)d_in[3];
    const float* gw2  = (const float*)d_in[4];
    const float* tcn  = (const float*)d_in[5];
    const float* bs   = (const float*)d_in[6];
    const float* bb   = (const float*)d_in[7];
    const float* bm   = (const float*)d_in[8];
    const float* bv   = (const float*)d_in[9];
    const float* lns  = (const float*)d_in[10];
    const float* lnb  = (const float*)d_in[11];
    const float* fcw  = (const float*)d_in[12];
    const float* fcb  = (const float*)d_in[13];
    float* out = (float*)d_out;

    float *buf1;
    uint32_t *y0h, *xa0, *xa1;
    cudaGetSymbolAddress((void**)&y0h, g_y0h);
    cudaGetSymbolAddress((void**)&buf1, g_buf1);
    cudaGetSymbolAddress((void**)&xa0, g_xa0);
    cudaGetSymbolAddress((void**)&xa1, g_xa1);

    int NTT = TILE_T + 2, XW = NTT*KPAD + 2;
    size_t s0 = (size_t)(272*YW + ((3*XW + 3) & ~3) + 3*3*HID + 308 + 64
                         + 289 + 289 + 20) * sizeof(float);
    cudaFuncSetAttribute(stblock0, cudaFuncAttributeMaxDynamicSharedMemorySize, (int)s0);
    cudaFuncSetAttribute(mma_kernel<17,false,true>, cudaFuncAttributeMaxDynamicSharedMemorySize, SMEM_MMA);
    cudaFuncSetAttribute(mma_kernel<34,true,false>, cudaFuncAttributeMaxDynamicSharedMemorySize, SMEM_MMA);

    prep_kernel<<<dim3(3,3), 64>>>(adj, gw0, gw1, gw2, tcn, bs, bb, bm, bv);
    zero_pads<<<dim3(32,16), 256>>>();

    dim3 grid0(NT, B_SZ);
    stblock0<<<grid0, 288, s0>>>(kpts, y0h, adj);

    mma_kernel<17,false,true><<<NTILES, 128, SMEM_MMA>>>(y0h, buf1, xa0, xa1, 0, 1);

    clean_premix<<<dim3(TILES_PB-1, B_SZ), 288>>>(buf1);

    mma_kernel<34,true,false><<<NTILES, 128, SMEM_MMA>>>(nullptr, nullptr, xa1, nullptr, 1, 2);

    finalize_kernel<<<B_SZ, 64>>>(lns, lnb, fcw, fcb, out);
}

// round 16
// speedup vs baseline: 1.0664x; 1.0664x over previous
#include <cuda_runtime.h>
#include <cuda_bf16.h>
#include <cuda_fp16.h>
#include <cstdint>

#define T_LEN 2048
#define KP    17
#define KPAD  18
#define HID   64
#define B_SZ  32
#define NCLS  10
#define TILE_T 16
#define NT    (T_LEN / TILE_T)
#define RPB   (T_LEN * KP)            // 34816 rows per batch
#define TILES_PB (RPB / 128)          // 272
#define NTILES (TILES_PB * B_SZ)      // 8704
#define PAD   64
#define PADROWS (RPB + 2*PAD)
#define KWPAD 100
#define HDR   4096
#define SBH_BYTES (64*KWPAD*4)        // 25600
#define SMEM_MMA (HDR + SBH_BYTES)    // 29696
#define YW2   33                      // ysm word stride (half2 words per row)

typedef unsigned long long ull;

__device__ uint32_t g_y0h[(size_t)B_SZ * RPB * 32];       // fp16 y0 (residual stream)
__device__ float    g_buf1[(size_t)B_SZ * RPB * HID];
__device__ uint32_t g_xa0[(size_t)B_SZ * PADROWS * 32];   // fp16 premixed layer-1 A
__device__ uint32_t g_xa1[(size_t)B_SZ * PADROWS * 32];   // fp16 premixed layer-2 A
__device__ float    g_Wf[3][3 * HID * HID];
__device__ unsigned short g_Wh[2][64 * 192];   // fp16 weights
__device__ float    g_beta[3][HID];
__device__ int      g_nnz[KP];
__device__ int      g_vidx[KP][KP];   // zero-padded to 4 entries
__device__ float    g_vw[KP][KP];
__device__ float    g_part[(size_t)NTILES * 64];
__device__ float    g_part1[(size_t)NTILES * 64];

// word position within a row for channel-pair c2 (LDG.128-friendly layout):
__device__ __forceinline__ int wpos(int c2) {
    return ((c2 & 3) << 3) | ((c2 >> 3) << 1) | ((c2 >> 2) & 1);
}
// c2 for pair-index p in 0..15 such that (c2, c2+4) -> (wpos, wpos+1)
__device__ __forceinline__ int c2base(int p) {
    return (p & 3) | ((p >> 2) << 3);
}

// ---------------- helpers ---------------------------------------------------
__device__ __forceinline__ void fma2(ull& d, ull a, ull b) {
    asm("fma.rn.f32x2 %0, %1, %2, %3;" : "=l"(d) : "l"(a), "l"(b), "l"(d));
}
__device__ __forceinline__ ull pack2(float x, float y) {
    ull r; asm("mov.b64 %0, {%1, %2};" : "=l"(r) : "f"(x), "f"(y)); return r;
}
__device__ __forceinline__ float2 unpack2(ull v) {
    float2 r; asm("mov.b64 {%0, %1}, %2;" : "=f"(r.x), "=f"(r.y) : "l"(v)); return r;
}
__device__ __forceinline__ uint32_t f16pack(float x, float y) {   // x -> low half
    uint32_t r;
    asm("cvt.rn.f16x2.f32 %0, %1, %2;" : "=r"(r) : "f"(y), "f"(x));
    return r;
}
__device__ __forceinline__ __half2 u2h2(uint32_t v) {
    return *reinterpret_cast<__half2*>(&v);
}
__device__ __forceinline__ uint32_t h22u(__half2 h) {
    return *reinterpret_cast<uint32_t*>(&h);
}
__device__ __forceinline__ uint32_t s2u(const void* p) {
    uint32_t a;
    asm("{ .reg .u64 t; cvta.to.shared.u64 t, %1; cvt.u32.u64 %0, t; }" : "=r"(a) : "l"(p));
    return a;
}
__device__ __forceinline__ void ldm4(uint32_t* r, uint32_t addr) {
    asm volatile("ldmatrix.sync.aligned.m8n8.x4.shared.b16 {%0,%1,%2,%3}, [%4];"
        : "=r"(r[0]), "=r"(r[1]), "=r"(r[2]), "=r"(r[3]) : "r"(addr));
}
__device__ __forceinline__ void mma_f16(float* d, const uint32_t* a, uint32_t b0, uint32_t b1) {
    asm volatile("mma.sync.aligned.m16n8k16.row.col.f32.f16.f16.f32 "
        "{%0,%1,%2,%3}, {%4,%5,%6,%7}, {%8,%9}, {%0,%1,%2,%3};"
        : "+f"(d[0]), "+f"(d[1]), "+f"(d[2]), "+f"(d[3])
        : "r"(a[0]), "r"(a[1]), "r"(a[2]), "r"(a[3]), "r"(b0), "r"(b1));
}

// ---------------------------------------------------------------------------
// prep: BN-folded fused weights; fp16 weights (layers 1,2); CSR adj
// ---------------------------------------------------------------------------
__global__ void prep_kernel(const float* __restrict__ adj,
                            const float* __restrict__ gw0, const float* __restrict__ gw1,
                            const float* __restrict__ gw2, const float* __restrict__ tcn,
                            const float* __restrict__ bs, const float* __restrict__ bb,
                            const float* __restrict__ bm, const float* __restrict__ bv)
{
    int blk = blockIdx.x, tau = blockIdx.y, o = threadIdx.x;
    const float* gw = (blk == 0) ? gw0 : ((blk == 1) ? gw1 : gw2);
    int CIN = (blk == 0) ? 3 : 64;
    float rstd = rsqrtf(bv[blk*64 + o] + 1e-5f);
    float inv  = bs[blk*64 + o] * rstd;
    if (tau == 0)
        g_beta[blk][o] = bb[blk*64 + o] - bs[blk*64 + o] * bm[blk*64 + o] * rstd;
    if (blk == 0 && tau == 0 && o < KP) {
        int n = 0;
        for (int v = 0; v < KP; v++) {
            float w = adj[v*KP + o];
            if (w != 0.f) { g_vidx[o][n] = v; g_vw[o][n] = w; n++; }
        }
        for (int i = n; i < 4; i++) { g_vidx[o][i] = 0; g_vw[o][i] = 0.f; }
        g_nnz[o] = n;
    }
    const float* tw = tcn + (size_t)blk * HID * HID * 3;
    for (int j = 0; j < CIN; j++) {
        float s = 0.f;
        for (int i = 0; i < HID; i++)
            s += gw[j*HID + i] * tw[(o*HID + i)*3 + tau];
        float val = s * inv;
        g_Wf[blk][(tau*CIN + j)*HID + o] = val;
        if (blk >= 1) {
            __half h = __float2half(val);
            g_Wh[blk-1][o*192 + tau*64 + j] = reinterpret_cast<unsigned short&>(h);
        }
    }
}

// ---------------------------------------------------------------------------
// zero pad rows of g_xa0 / g_xa1
// ---------------------------------------------------------------------------
__global__ void zero_pads()
{
    int b = blockIdx.x;
    int u = blockIdx.y * 256 + threadIdx.x;
    int o = u >> 5, w = u & 31;
    size_t pr = (size_t)b*PADROWS + (o < PAD ? o : (size_t)(PAD + RPB + (o - PAD)));
    g_xa0[pr*32 + w] = 0u;
    g_xa1[pr*32 + w] = 0u;
}

// ---------------------------------------------------------------------------
// cleanup premix: t-groups straddling a 128-row tile boundary (layer-2 input)
// ---------------------------------------------------------------------------
__global__ __launch_bounds__(288)
void clean_premix(const float* __restrict__ y)
{
    int k = blockIdx.x + 1;           // boundary index within batch, 1..271
    if (k % 17 == 0) return;
    int b = blockIdx.y;
    int g = (k * 128) / 17;           // straddling group
    int tid = threadIdx.x;
    const float* ybase = y + ((size_t)b*RPB + (size_t)g*17)*64;
    for (int u = tid; u < 17*16; u += 288) {
        int kk = u >> 4, p = u & 15;
        int c2 = c2base(p);
        ull accA = 0ull, accB = 0ull;
        #pragma unroll
        for (int i = 0; i < 4; i++) {
            float wv = g_vw[kk][i];
            ull wd = pack2(wv, wv);
            const float* yr = ybase + g_vidx[kk][i]*64 + 2*c2;
            fma2(accA, wd, *(const ull*)yr);
            fma2(accB, wd, *(const ull*)(yr + 8));
        }
        float2 a = unpack2(accA), c = unpack2(accB);
        size_t pr = (size_t)b*PADROWS + PAD + (size_t)g*17 + kk;
        int pos = wpos(c2);
        *(uint2*)(g_xa1 + pr*32 + pos) = make_uint2(f16pack(a.x, a.y), f16pack(c.x, c.y));
    }
}

// ---------------------------------------------------------------------------
// mma.sync GEMM layer: single-pass fp16 (A fp16 premixed, B fp16 in smem,
// fp32 accum). 1 tile/CTA; A hoisted per-tau (full 8x uint4), 32-bit indexing.
// FUSE (layer1): residual read from fp16 y0h; premix layer-2 input in-smem
//   (fp16 half2 math) -> g_xa1; y1 written (fp32) only for boundary rows;
//   pool y1 -> g_part1.
// POOL (layer2): pool relu(z+beta) -> g_part.
// ---------------------------------------------------------------------------
template<int SH, bool POOL, bool FUSE>
__global__ __launch_bounds__(128, 4)
void mma_kernel(const uint32_t* __restrict__ xres, float* __restrict__ yout,
                const uint32_t* __restrict__ xa, uint32_t* __restrict__ xaout,
                int wsel, int blk)
{
    extern __shared__ char smem[];
    // header [0, HDR): sbias(64f) pw(256f) svwh(289u) svix(289i)
    float*    sbias = (float*)smem;
    float*    pw    = sbias + 64;
    uint32_t* svwh  = (uint32_t*)(pw + 256);
    int*      svix  = (int*)(svwh + 289);
    // B region at HDR; ysm (fp16x2 words) reuses it post-mainloop
    uint32_t* sBh   = (uint32_t*)(smem + HDR);
    uint32_t* ysmw  = (uint32_t*)(smem + HDR);

    const int tid  = threadIdx.x;
    const int w    = tid >> 5;
    const int lane = tid & 31;
    const int grp  = lane >> 2;
    const int thr  = lane & 3;

    {
        const uint4* wh4 = (const uint4*)g_Wh[wsel];
        for (int u = tid; u < 64*24; u += 128) {
            int n = u / 24, q = u - n*24;
            *(uint4*)((char*)sBh + n*KWPAD*4 + q*16) = wh4[u];
        }
        if (tid < 64) sbias[tid] = g_beta[blk][tid];
        if (FUSE) {
            for (int u = tid; u < 289; u += 128) {
                float wv = ((const float*)g_vw)[u];
                svwh[u] = f16pack(wv, wv);
                svix[u] = ((const int*)g_vidx)[u];
            }
        }
    }
    __syncthreads();

    const uint32_t sb = s2u(smem);
    const int rowsel = (lane & 7) + ((lane >> 4) << 3);
    const int kq     = ((lane >> 3) & 1) * 4;
    const uint32_t bAH = sb + HDR + (uint32_t)(rowsel*KWPAD + kq)*4;

    const int tile = blockIdx.x;
    const int b    = tile / TILES_PB;
    const int r0b  = (tile - b*TILES_PB)*128;      // batch-local tile row base
    const int rloc = r0b + w*32 + grp;
    const uint32_t prow0 = (uint32_t)b*PADROWS + PAD + rloc;

    float C[2][8][4];
    #pragma unroll
    for (int mi = 0; mi < 2; mi++)
        #pragma unroll
        for (int nf = 0; nf < 8; nf++)
            #pragma unroll
            for (int q = 0; q < 4; q++) C[mi][nf][q] = 0.f;

    #pragma unroll
    for (int ti = 0; ti < 3; ti++) {
        const uint32_t base = (prow0 + (ti - 1)*SH)*32 + thr*8;
        uint4 H[2][2][2];     // [mi][row0/row8][lo4/hi4]
        #pragma unroll
        for (int mi = 0; mi < 2; mi++) {
            const uint4* p0 = (const uint4*)(xa + base + mi*512);
            const uint4* p1 = (const uint4*)(xa + base + mi*512 + 256);
            H[mi][0][0] = p0[0]; H[mi][0][1] = p0[1];
            H[mi][1][0] = p1[0]; H[mi][1][1] = p1[1];
        }
        #pragma unroll
        for (int ks = 0; ks < 4; ks++) {
            const int kstep = ti*4 + ks;
            #pragma unroll
            for (int p = 0; p < 4; p++) {
                uint32_t bh[4];
                ldm4(bh, bAH + (uint32_t)(p*16*KWPAD*4 + kstep*32));
                #pragma unroll
                for (int mi = 0; mi < 2; mi++) {
                    uint32_t ah[4];
                    uint4 U = H[mi][0][ks >> 1];
                    uint4 V = H[mi][1][ks >> 1];
                    if ((ks & 1) == 0) { ah[0]=U.x; ah[2]=U.y; ah[1]=V.x; ah[3]=V.y; }
                    else               { ah[0]=U.z; ah[2]=U.w; ah[1]=V.z; ah[3]=V.w; }
                    mma_f16(C[mi][2*p],   ah, bh[0], bh[1]);
                    mma_f16(C[mi][2*p+1], ah, bh[2], bh[3]);
                }
            }
        }
    }

    if (FUSE) __syncthreads();    // B reads complete; ysm may overwrite B

    const int gstart = (r0b + 16) / 17;
    const int glast  = (r0b + 111) / 17;

    // ---- epilogue ----
    const uint32_t grow_base = (uint32_t)tile*128 + w*32 + grp;
    float csum[16];
    #pragma unroll
    for (int u = 0; u < 16; u++) csum[u] = 0.f;

    #pragma unroll
    for (int mi = 0; mi < 2; mi++) {
        #pragma unroll
        for (int h = 0; h < 2; h++) {
            uint32_t gr = grow_base + mi*16 + h*8;
            const int lrow = w*32 + grp + mi*16 + h*8;
            bool wr = true;
            if (FUSE) {
                int gidx = (r0b + lrow) / 17;
                wr = (gidx < gstart) || (gidx > glast);
            }
            const uint32_t* xr = xres + (size_t)gr*32;
            #pragma unroll
            for (int nf = 0; nf < 8; nf++) {
                int c2i = nf*4 + thr;
                float2 bsv = *(const float2*)(sbias + c2i*2);
                float o0 = fmaxf(C[mi][nf][2*h]   + bsv.x, 0.f);
                float o1 = fmaxf(C[mi][nf][2*h+1] + bsv.y, 0.f);
                if (!POOL) {
                    float2 xv = __half22float2(u2h2(xr[c2i]));   // fp16 residual
                    o0 += xv.x; o1 += xv.y;
                    if (!FUSE || wr) {
                        float2* yr = (float2*)(yout + (size_t)gr*64);
                        yr[c2i] = make_float2(o0, o1);
                    }
                    if (FUSE)
                        ysmw[lrow*YW2 + c2i] = f16pack(o0, o1);
                }
                csum[2*nf]   += o0;
                csum[2*nf+1] += o1;
            }
        }
    }
    if (POOL || FUSE) {
        #pragma unroll
        for (int u = 0; u < 16; u++) {
            csum[u] += __shfl_xor_sync(0xffffffffu, csum[u], 4);
            csum[u] += __shfl_xor_sync(0xffffffffu, csum[u], 8);
            csum[u] += __shfl_xor_sync(0xffffffffu, csum[u], 16);
        }
        if (grp == 0) {
            #pragma unroll
            for (int nf = 0; nf < 8; nf++) {
                pw[w*64 + nf*8 + thr*2]     = csum[2*nf];
                pw[w*64 + nf*8 + thr*2 + 1] = csum[2*nf+1];
            }
        }
        __syncthreads();                      // also orders ysm for premix
        if (tid < 64) {
            float v = pw[tid] + pw[64 + tid] + pw[128 + tid] + pw[192 + tid];
            if (POOL) g_part[(size_t)tile*64 + tid] = v;
            else      g_part1[(size_t)tile*64 + tid] = v;
        }
    }

    if (FUSE) {
        const int nitems = (glast - gstart + 1) * (17*16);
        const uint32_t bnk = (uint32_t)b*PADROWS + PAD;
        for (int u = tid; u < nitems; u += 128) {
            int rig = u >> 4, p = u & 15;
            int c2 = c2base(p);
            int gq  = rig / 17;
            int kk  = rig - gq*17;
            int g   = gstart + gq;
            int gr  = g*17 + kk;                 // row within batch
            const int lbase = g*17 - r0b;
            __half2 accA = __float2half2_rn(0.f);
            __half2 accB = __float2half2_rn(0.f);
            #pragma unroll
            for (int i = 0; i < 4; i++) {
                __half2 wd = u2h2(svwh[kk*17 + i]);
                const uint32_t* yr = ysmw + (lbase + svix[kk*17 + i])*YW2;
                accA = __hfma2(u2h2(yr[c2]),     wd, accA);
                accB = __hfma2(u2h2(yr[c2 + 4]), wd, accB);
            }
            uint32_t pr = bnk + gr;
            int pos = wpos(c2);
            *(uint2*)(xaout + (size_t)pr*32 + pos) = make_uint2(h22u(accA), h22u(accB));
        }
    }
}

// ---------------------------------------------------------------------------
// Layer 0 (CIN=3) fp32 f32x2 kernel + FUSED premix of layer-1 input (fp16);
// y0 stored as fp16 half2 words (residual stream for layer 1).
// ---------------------------------------------------------------------------
#define YW 68
__global__ __launch_bounds__(288, 2)
void stblock0(const float* __restrict__ xin, uint32_t* __restrict__ youth,
              const float* __restrict__ adjg)
{
    constexpr int CIN = 3, D = 1;
    constexpr int NTT  = TILE_T + 2*D;
    constexpr int XW   = NTT*KPAD + 2;
    constexpr int XS   = ((CIN*XW + 3) & ~3);
    constexpr int WS_SZ = 3*CIN*HID;
    constexpr int YSM  = 272*YW;

    extern __shared__ float sm[];
    float* ysm  = sm;
    float* xg   = sm + YSM;
    float* Ws   = xg + XS;
    float* sadj = Ws + WS_SZ;
    float* sbet = sadj + 308;
    float* svw  = sbet + 64;
    int*   svix = (int*)(svw + 289);

    const int tid = threadIdx.x;
    const int b   = blockIdx.y;
    const int t0  = blockIdx.x * TILE_T;

    for (int u = tid; u < KP*KPAD; u += 288) {
        int v = u / KPAD, k = u - v*KPAD;
        sadj[u] = (k < KP) ? adjg[v*KP + k] : 0.f;
    }
    if (tid < HID) sbet[tid] = g_beta[0][tid];
    for (int u = tid; u < WS_SZ; u += 288) Ws[u] = g_Wf[0][u];
    for (int u = tid; u < 289; u += 288) {
        svw[u]  = ((const float*)g_vw)[u];
        svix[u] = ((const int*)g_vidx)[u];
    }
    __syncthreads();

    const float* xb = xin + (size_t)b * T_LEN * KP * CIN;
    for (int u = tid; u < NTT * CIN; u += 288) {
        int tl = u / CIN, c = u - tl*CIN;
        int tg = t0 + tl - D;
        float raw[KP];
        if (tg >= 0 && tg < T_LEN) {
            const float* xr = xb + (size_t)tg * KP * CIN + c;
            #pragma unroll
            for (int v = 0; v < KP; v++) raw[v] = __ldg(xr + v*CIN);
        } else {
            #pragma unroll
            for (int v = 0; v < KP; v++) raw[v] = 0.f;
        }
        ull s2[KPAD/2];
        #pragma unroll
        for (int p = 0; p < KPAD/2; p++) s2[p] = 0ull;
        #pragma unroll
        for (int v = 0; v < KP; v++) {
            ull rd = pack2(raw[v], raw[v]);
            const ull* ap = (const ull*)(sadj + v*KPAD);
            #pragma unroll
            for (int p = 0; p < KPAD/2; p++) fma2(s2[p], rd, ap[p]);
        }
        ull* xo = (ull*)(xg + c*XW + tl*KPAD);
        #pragma unroll
        for (int p = 0; p < KPAD/2; p++) xo[p] = s2[p];
    }
    __syncthreads();

    const int cg = tid & 7;
    const int rg = tid >> 3;
    const int r0 = rg * 8;

    ull acc[4][8];
    #pragma unroll
    for (int q = 0; q < 4; q++)
        #pragma unroll
        for (int p = 0; p < 8; p++) acc[q][p] = 0ull;

    #pragma unroll
    for (int tau = 0; tau < 3; tau++) {
        const float* wsrc = Ws + tau*CIN*HID;
        const float* xpb = xg + tau*(KPAD*D) + r0;
        #pragma unroll
        for (int j = 0; j < CIN; j++) {
            const ull* xp = (const ull*)(xpb + j*XW);
            ull x0 = xp[0], x1 = xp[1], x2 = xp[2], x3 = xp[3];
            const float* wr = wsrc + j*HID + cg*8;
            float4 wa = *(const float4*)(wr);
            float4 wb = *(const float4*)(wr + 4);
            ull wd[8];
            wd[0] = pack2(wa.x, wa.x); wd[1] = pack2(wa.y, wa.y);
            wd[2] = pack2(wa.z, wa.z); wd[3] = pack2(wa.w, wa.w);
            wd[4] = pack2(wb.x, wb.x); wd[5] = pack2(wb.y, wb.y);
            wd[6] = pack2(wb.z, wb.z); wd[7] = pack2(wb.w, wb.w);
            #pragma unroll
            for (int p = 0; p < 8; p++) {
                fma2(acc[0][p], x0, wd[p]);
                fma2(acc[1][p], x1, wd[p]);
                fma2(acc[2][p], x2, wd[p]);
                fma2(acc[3][p], x3, wd[p]);
            }
        }
    }

    const float4 bA = *(const float4*)(sbet + cg*8);
    const float4 bB = *(const float4*)(sbet + cg*8 + 4);
    #pragma unroll
    for (int q = 0; q < 4; q++) {
        float vr[2][8];
        #pragma unroll
        for (int p = 0; p < 8; p++) {
            float2 u2 = unpack2(acc[q][p]);
            vr[0][p] = u2.x; vr[1][p] = u2.y;
        }
        #pragma unroll
        for (int h = 0; h < 2; h++) {
            int r  = r0 + 2*q + h;
            int tl = r / KPAD;
            int kk = r - tl*KPAD;
            if (kk < KP) {
                size_t grow = ((size_t)b*T_LEN + (t0 + tl))*KP + kk;
                float o[8];
                o[0] = fmaxf(vr[h][0] + bA.x, 0.f);
                o[1] = fmaxf(vr[h][1] + bA.y, 0.f);
                o[2] = fmaxf(vr[h][2] + bA.z, 0.f);
                o[3] = fmaxf(vr[h][3] + bA.w, 0.f);
                o[4] = fmaxf(vr[h][4] + bB.x, 0.f);
                o[5] = fmaxf(vr[h][5] + bB.y, 0.f);
                o[6] = fmaxf(vr[h][6] + bB.z, 0.f);
                o[7] = fmaxf(vr[h][7] + bB.w, 0.f);
                uint4 hv;
                hv.x = f16pack(o[0], o[1]); hv.y = f16pack(o[2], o[3]);
                hv.z = f16pack(o[4], o[5]); hv.w = f16pack(o[6], o[7]);
                *(uint4*)(youth + grow*32 + cg*4) = hv;
                int yr = tl*KP + kk;
                *(float4*)(ysm + yr*YW + cg*8)     = make_float4(o[0], o[1], o[2], o[3]);
                *(float4*)(ysm + yr*YW + cg*8 + 4) = make_float4(o[4], o[5], o[6], o[7]);
            }
        }
    }
    __syncthreads();

    // ---- fused premix: layer-1 A = adj * y0 (packed, fixed-4 unroll, fp16) ----
    const size_t bnk = ((size_t)b*PADROWS + PAD + (size_t)t0*KP);
    for (int u = tid; u < 272*16; u += 288) {
        int row = u >> 4, p = u & 15;
        int c2 = c2base(p);
        int tl = row / KP, kk = row - tl*KP;
        const float* yb = ysm + tl*KP*YW + 2*c2;
        ull accA = 0ull, accB = 0ull;
        #pragma unroll
        for (int i = 0; i < 4; i++) {
            float wv = svw[kk*17 + i];
            ull wd = pack2(wv, wv);
            const float* yr = yb + svix[kk*17 + i]*YW;
            fma2(accA, wd, *(const ull*)yr);
            fma2(accB, wd, *(const ull*)(yr + 8));
        }
        float2 a = unpack2(accA), c = unpack2(accB);
        size_t pr = bnk + row;
        int pos = wpos(c2);
        *(uint2*)(g_xa0 + pr*32 + pos) = make_uint2(f16pack(a.x, a.y), f16pack(c.x, c.y));
    }
}

// ---------------------------------------------------------------------------
// finalize: pool = Σ(g_part + g_part1) -> LayerNorm -> FC
// ---------------------------------------------------------------------------
__global__ void finalize_kernel(const float* __restrict__ lns, const float* __restrict__ lnb,
                                const float* __restrict__ fcw, const float* __restrict__ fcb,
                                float* __restrict__ out)
{
    int b = blockIdx.x;
    int c = threadIdx.x;
    float s = 0.f;
    const float* pp = g_part  + (size_t)b * TILES_PB * 64;
    const float* pq = g_part1 + (size_t)b * TILES_PB * 64;
    for (int t = 0; t < TILES_PB; t++) s += pp[t*64 + c] + pq[t*64 + c];
    s *= (1.f / ((float)T_LEN * (float)KP));

    __shared__ float red[64];
    __shared__ float sf[64];
    red[c] = s; __syncthreads();
    for (int off = 32; off; off >>= 1) { if (c < off) red[c] += red[c+off]; __syncthreads(); }
    float mu = red[0] * (1.f/64.f);
    __syncthreads();
    float d = s - mu;
    red[c] = d * d; __syncthreads();
    for (int off = 32; off; off >>= 1) { if (c < off) red[c] += red[c+off]; __syncthreads(); }
    float var = red[0] * (1.f/64.f);
    float f = d * rsqrtf(var + 1e-5f) * lns[c] + lnb[c];
    sf[c] = f; __syncthreads();
    if (c < NCLS) {
        float o = fcb[c];
        #pragma unroll
        for (int i = 0; i < 64; i++) o += sf[i] * fcw[i*NCLS + c];
        out[b*NCLS + c] = o;
    }
}

extern "C" void kernel_launch(void* const* d_in, const int* in_sizes, int n_in,
                              void* d_out, int out_size)
{
    const float* kpts = (const float*)d_in[0];
    const float* adj  = (const float*)d_in[1];
    const float* gw0  = (const float*)d_in[2];
    const float* gw1  = (const float*)d_in[3];
    const float* gw2  = (const float*)d_in[4];
    const float* tcn  = (const float*)d_in[5];
    const float* bs   = (const float*)d_in[6];
    const float* bb   = (const float*)d_in[7];
    const float* bm   = (const float*)d_in[8];
    const float* bv   = (const float*)d_in[9];
    const float* lns  = (const float*)d_in[10];
    const float* lnb  = (const float*)d_in[11];
    const float* fcw  = (const float*)d_in[12];
    const float* fcb  = (const float*)d_in[13];
    float* out = (float*)d_out;

    float *buf1;
    uint32_t *y0h, *xa0, *xa1;
    cudaGetSymbolAddress((void**)&y0h, g_y0h);
    cudaGetSymbolAddress((void**)&buf1, g_buf1);
    cudaGetSymbolAddress((void**)&xa0, g_xa0);
    cudaGetSymbolAddress((void**)&xa1, g_xa1);

    int NTT = TILE_T + 2, XW = NTT*KPAD + 2;
    size_t s0 = (size_t)(272*YW + ((3*XW + 3) & ~3) + 3*3*HID + 308 + 64
                         + 289 + 289 + 20) * sizeof(float);
    cudaFuncSetAttribute(stblock0, cudaFuncAttributeMaxDynamicSharedMemorySize, (int)s0);
    cudaFuncSetAttribute(mma_kernel<17,false,true>, cudaFuncAttributeMaxDynamicSharedMemorySize, SMEM_MMA);
    cudaFuncSetAttribute(mma_kernel<34,true,false>, cudaFuncAttributeMaxDynamicSharedMemorySize, SMEM_MMA);

    prep_kernel<<<dim3(3,3), 64>>>(adj, gw0, gw1, gw2, tcn, bs, bb, bm, bv);
    zero_pads<<<dim3(32,16), 256>>>();

    dim3 grid0(NT, B_SZ);
    stblock0<<<grid0, 288, s0>>>(kpts, y0h, adj);

    mma_kernel<17,false,true><<<NTILES, 128, SMEM_MMA>>>(y0h, buf1, xa0, xa1, 0, 1);

    clean_premix<<<dim3(TILES_PB-1, B_SZ), 288>>>(buf1);

    mma_kernel<34,true,false><<<NTILES, 128, SMEM_MMA>>>(nullptr, nullptr, xa1, nullptr, 1, 2);

    finalize_kernel<<<B_SZ, 64>>>(lns, lnb, fcw, fcb, out);
}

// round 17
// speedup vs baseline: 1.0937x; 1.0256x over previous
#include <cuda_runtime.h>
#include <cuda_bf16.h>
#include <cuda_fp16.h>
#include <cstdint>

#define T_LEN 2048
#define KP    17
#define KPAD  18
#define HID   64
#define B_SZ  32
#define NCLS  10
#define TILE_T 16
#define NT    (T_LEN / TILE_T)
#define RPB   (T_LEN * KP)            // 34816 rows per batch
#define TILES_PB (RPB / 128)          // 272
#define NTILES (TILES_PB * B_SZ)      // 8704
#define PAD   64
#define PADROWS (RPB + 2*PAD)
#define KWPAD 100
#define HDR   4096
#define SBH_BYTES (64*KWPAD*4)        // 25600
#define SMEM_MMA (HDR + SBH_BYTES)    // 29696
#define YW2X  34                      // permuted ysm stride (uint32 words per row)

typedef unsigned long long ull;

__device__ uint32_t g_y0h[(size_t)B_SZ * RPB * 32];       // fp16 y0 (residual stream)
__device__ float    g_buf1[(size_t)B_SZ * RPB * HID];
__device__ uint32_t g_xa0[(size_t)B_SZ * PADROWS * 32];   // fp16 premixed layer-1 A
__device__ uint32_t g_xa1[(size_t)B_SZ * PADROWS * 32];   // fp16 premixed layer-2 A
__device__ float    g_Wf[3][3 * HID * HID];
__device__ unsigned short g_Wh[2][64 * 192];   // fp16 weights
__device__ float    g_beta[3][HID];
__device__ int      g_nnz[KP];
__device__ int      g_vidx[KP][KP];   // zero-padded to 4 entries
__device__ float    g_vw[KP][KP];
__device__ float    g_part[(size_t)NTILES * 64];
__device__ float    g_part1[(size_t)NTILES * 64];

// word position within a row for channel-pair c2 (LDG.128-friendly layout):
__device__ __forceinline__ int wpos(int c2) {
    return ((c2 & 3) << 3) | ((c2 >> 3) << 1) | ((c2 >> 2) & 1);
}
// c2 for pair-index p in 0..15 such that (c2, c2+4) -> (wpos, wpos+1)
__device__ __forceinline__ int c2base(int p) {
    return (p & 3) | ((p >> 2) << 3);
}

// ---------------- helpers ---------------------------------------------------
__device__ __forceinline__ void fma2(ull& d, ull a, ull b) {
    asm("fma.rn.f32x2 %0, %1, %2, %3;" : "=l"(d) : "l"(a), "l"(b), "l"(d));
}
__device__ __forceinline__ ull pack2(float x, float y) {
    ull r; asm("mov.b64 %0, {%1, %2};" : "=l"(r) : "f"(x), "f"(y)); return r;
}
__device__ __forceinline__ float2 unpack2(ull v) {
    float2 r; asm("mov.b64 {%0, %1}, %2;" : "=f"(r.x), "=f"(r.y) : "l"(v)); return r;
}
__device__ __forceinline__ uint32_t f16pack(float x, float y) {   // x -> low half
    uint32_t r;
    asm("cvt.rn.f16x2.f32 %0, %1, %2;" : "=r"(r) : "f"(y), "f"(x));
    return r;
}
__device__ __forceinline__ __half2 u2h2(uint32_t v) {
    return *reinterpret_cast<__half2*>(&v);
}
__device__ __forceinline__ uint32_t h22u(__half2 h) {
    return *reinterpret_cast<uint32_t*>(&h);
}
__device__ __forceinline__ uint32_t s2u(const void* p) {
    uint32_t a;
    asm("{ .reg .u64 t; cvta.to.shared.u64 t, %1; cvt.u32.u64 %0, t; }" : "=r"(a) : "l"(p));
    return a;
}
__device__ __forceinline__ void ldm4(uint32_t* r, uint32_t addr) {
    asm volatile("ldmatrix.sync.aligned.m8n8.x4.shared.b16 {%0,%1,%2,%3}, [%4];"
        : "=r"(r[0]), "=r"(r[1]), "=r"(r[2]), "=r"(r[3]) : "r"(addr));
}
__device__ __forceinline__ void mma_f16(float* d, const uint32_t* a, uint32_t b0, uint32_t b1) {
    asm volatile("mma.sync.aligned.m16n8k16.row.col.f32.f16.f16.f32 "
        "{%0,%1,%2,%3}, {%4,%5,%6,%7}, {%8,%9}, {%0,%1,%2,%3};"
        : "+f"(d[0]), "+f"(d[1]), "+f"(d[2]), "+f"(d[3])
        : "r"(a[0]), "r"(a[1]), "r"(a[2]), "r"(a[3]), "r"(b0), "r"(b1));
}

// ---------------------------------------------------------------------------
// prep: BN-folded fused weights; fp16 weights (layers 1,2); CSR adj
// ---------------------------------------------------------------------------
__global__ void prep_kernel(const float* __restrict__ adj,
                            const float* __restrict__ gw0, const float* __restrict__ gw1,
                            const float* __restrict__ gw2, const float* __restrict__ tcn,
                            const float* __restrict__ bs, const float* __restrict__ bb,
                            const float* __restrict__ bm, const float* __restrict__ bv)
{
    int blk = blockIdx.x, tau = blockIdx.y, o = threadIdx.x;
    const float* gw = (blk == 0) ? gw0 : ((blk == 1) ? gw1 : gw2);
    int CIN = (blk == 0) ? 3 : 64;
    float rstd = rsqrtf(bv[blk*64 + o] + 1e-5f);
    float inv  = bs[blk*64 + o] * rstd;
    if (tau == 0)
        g_beta[blk][o] = bb[blk*64 + o] - bs[blk*64 + o] * bm[blk*64 + o] * rstd;
    if (blk == 0 && tau == 0 && o < KP) {
        int n = 0;
        for (int v = 0; v < KP; v++) {
            float w = adj[v*KP + o];
            if (w != 0.f) { g_vidx[o][n] = v; g_vw[o][n] = w; n++; }
        }
        for (int i = n; i < 4; i++) { g_vidx[o][i] = 0; g_vw[o][i] = 0.f; }
        g_nnz[o] = n;
    }
    const float* tw = tcn + (size_t)blk * HID * HID * 3;
    for (int j = 0; j < CIN; j++) {
        float s = 0.f;
        for (int i = 0; i < HID; i++)
            s += gw[j*HID + i] * tw[(o*HID + i)*3 + tau];
        float val = s * inv;
        g_Wf[blk][(tau*CIN + j)*HID + o] = val;
        if (blk >= 1) {
            __half h = __float2half(val);
            g_Wh[blk-1][o*192 + tau*64 + j] = reinterpret_cast<unsigned short&>(h);
        }
    }
}

// ---------------------------------------------------------------------------
// zero pad rows of g_xa0 / g_xa1
// ---------------------------------------------------------------------------
__global__ void zero_pads()
{
    int b = blockIdx.x;
    int u = blockIdx.y * 256 + threadIdx.x;
    int o = u >> 5, w = u & 31;
    size_t pr = (size_t)b*PADROWS + (o < PAD ? o : (size_t)(PAD + RPB + (o - PAD)));
    g_xa0[pr*32 + w] = 0u;
    g_xa1[pr*32 + w] = 0u;
}

// ---------------------------------------------------------------------------
// cleanup premix: t-groups straddling a 128-row tile boundary (layer-2 input)
// ---------------------------------------------------------------------------
__global__ __launch_bounds__(288)
void clean_premix(const float* __restrict__ y)
{
    int k = blockIdx.x + 1;           // boundary index within batch, 1..271
    if (k % 17 == 0) return;
    int b = blockIdx.y;
    int g = (k * 128) / 17;           // straddling group
    int tid = threadIdx.x;
    const float* ybase = y + ((size_t)b*RPB + (size_t)g*17)*64;
    for (int u = tid; u < 17*16; u += 288) {
        int kk = u >> 4, p = u & 15;
        int c2 = c2base(p);
        ull accA = 0ull, accB = 0ull;
        #pragma unroll
        for (int i = 0; i < 4; i++) {
            float wv = g_vw[kk][i];
            ull wd = pack2(wv, wv);
            const float* yr = ybase + g_vidx[kk][i]*64 + 2*c2;
            fma2(accA, wd, *(const ull*)yr);
            fma2(accB, wd, *(const ull*)(yr + 8));
        }
        float2 a = unpack2(accA), c = unpack2(accB);
        size_t pr = (size_t)b*PADROWS + PAD + (size_t)g*17 + kk;
        int pos = wpos(c2);
        *(uint2*)(g_xa1 + pr*32 + pos) = make_uint2(f16pack(a.x, a.y), f16pack(c.x, c.y));
    }
}

// ---------------------------------------------------------------------------
// mma.sync GEMM layer: single-pass fp16 (A fp16 premixed, B fp16 in smem,
// fp32 accum). 1 tile/CTA; A hoisted per-tau (full 8x uint4), 32-bit indexing.
// FUSE (layer1): residual read from fp16 y0h; ysm staged in wpos-PERMUTED
//   order (STS.64 / LDS.64 pairs); premix layer-2 input in-smem -> g_xa1;
//   y1 written (fp32) only for boundary rows; pool y1 -> g_part1.
// POOL (layer2): pool relu(z+beta) -> g_part.
// ---------------------------------------------------------------------------
template<int SH, bool POOL, bool FUSE>
__global__ __launch_bounds__(128, 4)
void mma_kernel(const uint32_t* __restrict__ xres, float* __restrict__ yout,
                const uint32_t* __restrict__ xa, uint32_t* __restrict__ xaout,
                int wsel, int blk)
{
    extern __shared__ char smem[];
    // header [0, HDR): sbias(64f) pw(256f) svwh(289u) svix(289i)
    float*    sbias = (float*)smem;
    float*    pw    = sbias + 64;
    uint32_t* svwh  = (uint32_t*)(pw + 256);
    int*      svix  = (int*)(svwh + 289);
    // B region at HDR; ysm (fp16x2 words, PERMUTED) reuses it post-mainloop
    uint32_t* sBh   = (uint32_t*)(smem + HDR);
    uint32_t* ysmw  = (uint32_t*)(smem + HDR);

    const int tid  = threadIdx.x;
    const int w    = tid >> 5;
    const int lane = tid & 31;
    const int grp  = lane >> 2;
    const int thr  = lane & 3;

    {
        const uint4* wh4 = (const uint4*)g_Wh[wsel];
        for (int u = tid; u < 64*24; u += 128) {
            int n = u / 24, q = u - n*24;
            *(uint4*)((char*)sBh + n*KWPAD*4 + q*16) = wh4[u];
        }
        if (tid < 64) sbias[tid] = g_beta[blk][tid];
        if (FUSE) {
            for (int u = tid; u < 289; u += 128) {
                float wv = ((const float*)g_vw)[u];
                svwh[u] = f16pack(wv, wv);
                svix[u] = ((const int*)g_vidx)[u];
            }
        }
    }
    __syncthreads();

    const uint32_t sb = s2u(smem);
    const int rowsel = (lane & 7) + ((lane >> 4) << 3);
    const int kq     = ((lane >> 3) & 1) * 4;
    const uint32_t bAH = sb + HDR + (uint32_t)(rowsel*KWPAD + kq)*4;

    const int tile = blockIdx.x;
    const int b    = tile / TILES_PB;
    const int r0b  = (tile - b*TILES_PB)*128;      // batch-local tile row base
    const int rloc = r0b + w*32 + grp;
    const uint32_t prow0 = (uint32_t)b*PADROWS + PAD + rloc;

    float C[2][8][4];
    #pragma unroll
    for (int mi = 0; mi < 2; mi++)
        #pragma unroll
        for (int nf = 0; nf < 8; nf++)
            #pragma unroll
            for (int q = 0; q < 4; q++) C[mi][nf][q] = 0.f;

    #pragma unroll
    for (int ti = 0; ti < 3; ti++) {
        const uint32_t base = (prow0 + (ti - 1)*SH)*32 + thr*8;
        uint4 H[2][2][2];     // [mi][row0/row8][lo4/hi4]
        #pragma unroll
        for (int mi = 0; mi < 2; mi++) {
            const uint4* p0 = (const uint4*)(xa + base + mi*512);
            const uint4* p1 = (const uint4*)(xa + base + mi*512 + 256);
            H[mi][0][0] = p0[0]; H[mi][0][1] = p0[1];
            H[mi][1][0] = p1[0]; H[mi][1][1] = p1[1];
        }
        #pragma unroll
        for (int ks = 0; ks < 4; ks++) {
            const int kstep = ti*4 + ks;
            #pragma unroll
            for (int p = 0; p < 4; p++) {
                uint32_t bh[4];
                ldm4(bh, bAH + (uint32_t)(p*16*KWPAD*4 + kstep*32));
                #pragma unroll
                for (int mi = 0; mi < 2; mi++) {
                    uint32_t ah[4];
                    uint4 U = H[mi][0][ks >> 1];
                    uint4 V = H[mi][1][ks >> 1];
                    if ((ks & 1) == 0) { ah[0]=U.x; ah[2]=U.y; ah[1]=V.x; ah[3]=V.y; }
                    else               { ah[0]=U.z; ah[2]=U.w; ah[1]=V.z; ah[3]=V.w; }
                    mma_f16(C[mi][2*p],   ah, bh[0], bh[1]);
                    mma_f16(C[mi][2*p+1], ah, bh[2], bh[3]);
                }
            }
        }
    }

    if (FUSE) __syncthreads();    // B reads complete; ysm may overwrite B

    const int gstart = (r0b + 16) / 17;
    const int glast  = (r0b + 111) / 17;

    // ---- epilogue ----
    const uint32_t grow_base = (uint32_t)tile*128 + w*32 + grp;
    float csum[16];
    #pragma unroll
    for (int u = 0; u < 16; u++) csum[u] = 0.f;

    #pragma unroll
    for (int mi = 0; mi < 2; mi++) {
        #pragma unroll
        for (int h = 0; h < 2; h++) {
            uint32_t gr = grow_base + mi*16 + h*8;
            const int lrow = w*32 + grp + mi*16 + h*8;
            bool wr = true;
            if (FUSE) {
                int gidx = (r0b + lrow) / 17;
                wr = (gidx < gstart) || (gidx > glast);
            }
            const uint32_t* xr = xres + (size_t)gr*32;
            #pragma unroll
            for (int q = 0; q < 4; q++) {
                // nf pair (2q, 2q+1) -> channel pairs (c2a, c2a+4)
                int c2a = q*8 + thr;
                int c2b = c2a + 4;
                float2 bsa = *(const float2*)(sbias + c2a*2);
                float2 bsb = *(const float2*)(sbias + c2b*2);
                float a0 = fmaxf(C[mi][2*q][2*h]     + bsa.x, 0.f);
                float a1 = fmaxf(C[mi][2*q][2*h+1]   + bsa.y, 0.f);
                float b0 = fmaxf(C[mi][2*q+1][2*h]   + bsb.x, 0.f);
                float b1 = fmaxf(C[mi][2*q+1][2*h+1] + bsb.y, 0.f);
                if (!POOL) {
                    float2 xva = __half22float2(u2h2(xr[c2a]));
                    float2 xvb = __half22float2(u2h2(xr[c2b]));
                    a0 += xva.x; a1 += xva.y;
                    b0 += xvb.x; b1 += xvb.y;
                    if (!FUSE || wr) {
                        float2* yr = (float2*)(yout + (size_t)gr*64);
                        yr[c2a] = make_float2(a0, a1);
                        yr[c2b] = make_float2(b0, b1);
                    }
                    if (FUSE) {
                        int pos = thr*8 + q*2;     // = wpos(c2a); wpos(c2b)=pos+1
                        *(uint2*)(ysmw + lrow*YW2X + pos) =
                            make_uint2(f16pack(a0, a1), f16pack(b0, b1));
                    }
                }
                csum[4*q]   += a0;
                csum[4*q+1] += a1;
                csum[4*q+2] += b0;
                csum[4*q+3] += b1;
            }
        }
    }
    if (POOL || FUSE) {
        #pragma unroll
        for (int u = 0; u < 16; u++) {
            csum[u] += __shfl_xor_sync(0xffffffffu, csum[u], 4);
            csum[u] += __shfl_xor_sync(0xffffffffu, csum[u], 8);
            csum[u] += __shfl_xor_sync(0xffffffffu, csum[u], 16);
        }
        if (grp == 0) {
            #pragma unroll
            for (int nf = 0; nf < 8; nf++) {
                pw[w*64 + nf*8 + thr*2]     = csum[2*nf];
                pw[w*64 + nf*8 + thr*2 + 1] = csum[2*nf+1];
            }
        }
        __syncthreads();                      // also orders ysm for premix
        if (tid < 64) {
            float v = pw[tid] + pw[64 + tid] + pw[128 + tid] + pw[192 + tid];
            if (POOL) g_part[(size_t)tile*64 + tid] = v;
            else      g_part1[(size_t)tile*64 + tid] = v;
        }
    }

    if (FUSE) {
        const int nitems = (glast - gstart + 1) * (17*16);
        const uint32_t bnk = (uint32_t)b*PADROWS + PAD;
        for (int u = tid; u < nitems; u += 128) {
            int rig = u >> 4, p = u & 15;
            int pos = (p & 3)*8 + (p >> 2)*2;   // = wpos(c2base(p))
            int gq  = rig / 17;
            int kk  = rig - gq*17;
            int g   = gstart + gq;
            int gr  = g*17 + kk;                 // row within batch
            const int lbase = g*17 - r0b;
            __half2 accA = __float2half2_rn(0.f);
            __half2 accB = __float2half2_rn(0.f);
            #pragma unroll
            for (int i = 0; i < 4; i++) {
                __half2 wd = u2h2(svwh[kk*17 + i]);
                uint2 yv = *(const uint2*)(ysmw + (lbase + svix[kk*17 + i])*YW2X + pos);
                accA = __hfma2(u2h2(yv.x), wd, accA);
                accB = __hfma2(u2h2(yv.y), wd, accB);
            }
            uint32_t pr = bnk + gr;
            *(uint2*)(xaout + (size_t)pr*32 + pos) = make_uint2(h22u(accA), h22u(accB));
        }
    }
}

// ---------------------------------------------------------------------------
// Layer 0 (CIN=3) fp32 f32x2 kernel + FUSED premix of layer-1 input (fp16);
// y0 stored as fp16 half2 words (residual stream for layer 1).
// ---------------------------------------------------------------------------
#define YW 68
__global__ __launch_bounds__(288, 2)
void stblock0(const float* __restrict__ xin, uint32_t* __restrict__ youth,
              const float* __restrict__ adjg)
{
    constexpr int CIN = 3, D = 1;
    constexpr int NTT  = TILE_T + 2*D;
    constexpr int XW   = NTT*KPAD + 2;
    constexpr int XS   = ((CIN*XW + 3) & ~3);
    constexpr int WS_SZ = 3*CIN*HID;
    constexpr int YSM  = 272*YW;

    extern __shared__ float sm[];
    float* ysm  = sm;
    float* xg   = sm + YSM;
    float* Ws   = xg + XS;
    float* sadj = Ws + WS_SZ;
    float* sbet = sadj + 308;
    float* svw  = sbet + 64;
    int*   svix = (int*)(svw + 289);

    const int tid = threadIdx.x;
    const int b   = blockIdx.y;
    const int t0  = blockIdx.x * TILE_T;

    for (int u = tid; u < KP*KPAD; u += 288) {
        int v = u / KPAD, k = u - v*KPAD;
        sadj[u] = (k < KP) ? adjg[v*KP + k] : 0.f;
    }
    if (tid < HID) sbet[tid] = g_beta[0][tid];
    for (int u = tid; u < WS_SZ; u += 288) Ws[u] = g_Wf[0][u];
    for (int u = tid; u < 289; u += 288) {
        svw[u]  = ((const float*)g_vw)[u];
        svix[u] = ((const int*)g_vidx)[u];
    }
    __syncthreads();

    const float* xb = xin + (size_t)b * T_LEN * KP * CIN;
    for (int u = tid; u < NTT * CIN; u += 288) {
        int tl = u / CIN, c = u - tl*CIN;
        int tg = t0 + tl - D;
        float raw[KP];
        if (tg >= 0 && tg < T_LEN) {
            const float* xr = xb + (size_t)tg * KP * CIN + c;
            #pragma unroll
            for (int v = 0; v < KP; v++) raw[v] = __ldg(xr + v*CIN);
        } else {
            #pragma unroll
            for (int v = 0; v < KP; v++) raw[v] = 0.f;
        }
        ull s2[KPAD/2];
        #pragma unroll
        for (int p = 0; p < KPAD/2; p++) s2[p] = 0ull;
        #pragma unroll
        for (int v = 0; v < KP; v++) {
            ull rd = pack2(raw[v], raw[v]);
            const ull* ap = (const ull*)(sadj + v*KPAD);
            #pragma unroll
            for (int p = 0; p < KPAD/2; p++) fma2(s2[p], rd, ap[p]);
        }
        ull* xo = (ull*)(xg + c*XW + tl*KPAD);
        #pragma unroll
        for (int p = 0; p < KPAD/2; p++) xo[p] = s2[p];
    }
    __syncthreads();

    const int cg = tid & 7;
    const int rg = tid >> 3;
    const int r0 = rg * 8;

    ull acc[4][8];
    #pragma unroll
    for (int q = 0; q < 4; q++)
        #pragma unroll
        for (int p = 0; p < 8; p++) acc[q][p] = 0ull;

    #pragma unroll
    for (int tau = 0; tau < 3; tau++) {
        const float* wsrc = Ws + tau*CIN*HID;
        const float* xpb = xg + tau*(KPAD*D) + r0;
        #pragma unroll
        for (int j = 0; j < CIN; j++) {
            const ull* xp = (const ull*)(xpb + j*XW);
            ull x0 = xp[0], x1 = xp[1], x2 = xp[2], x3 = xp[3];
            const float* wr = wsrc + j*HID + cg*8;
            float4 wa = *(const float4*)(wr);
            float4 wb = *(const float4*)(wr + 4);
            ull wd[8];
            wd[0] = pack2(wa.x, wa.x); wd[1] = pack2(wa.y, wa.y);
            wd[2] = pack2(wa.z, wa.z); wd[3] = pack2(wa.w, wa.w);
            wd[4] = pack2(wb.x, wb.x); wd[5] = pack2(wb.y, wb.y);
            wd[6] = pack2(wb.z, wb.z); wd[7] = pack2(wb.w, wb.w);
            #pragma unroll
            for (int p = 0; p < 8; p++) {
                fma2(acc[0][p], x0, wd[p]);
                fma2(acc[1][p], x1, wd[p]);
                fma2(acc[2][p], x2, wd[p]);
                fma2(acc[3][p], x3, wd[p]);
            }
        }
    }

    const float4 bA = *(const float4*)(sbet + cg*8);
    const float4 bB = *(const float4*)(sbet + cg*8 + 4);
    #pragma unroll
    for (int q = 0; q < 4; q++) {
        float vr[2][8];
        #pragma unroll
        for (int p = 0; p < 8; p++) {
            float2 u2 = unpack2(acc[q][p]);
            vr[0][p] = u2.x; vr[1][p] = u2.y;
        }
        #pragma unroll
        for (int h = 0; h < 2; h++) {
            int r  = r0 + 2*q + h;
            int tl = r / KPAD;
            int kk = r - tl*KPAD;
            if (kk < KP) {
                size_t grow = ((size_t)b*T_LEN + (t0 + tl))*KP + kk;
                float o[8];
                o[0] = fmaxf(vr[h][0] + bA.x, 0.f);
                o[1] = fmaxf(vr[h][1] + bA.y, 0.f);
                o[2] = fmaxf(vr[h][2] + bA.z, 0.f);
                o[3] = fmaxf(vr[h][3] + bA.w, 0.f);
                o[4] = fmaxf(vr[h][4] + bB.x, 0.f);
                o[5] = fmaxf(vr[h][5] + bB.y, 0.f);
                o[6] = fmaxf(vr[h][6] + bB.z, 0.f);
                o[7] = fmaxf(vr[h][7] + bB.w, 0.f);
                uint4 hv;
                hv.x = f16pack(o[0], o[1]); hv.y = f16pack(o[2], o[3]);
                hv.z = f16pack(o[4], o[5]); hv.w = f16pack(o[6], o[7]);
                *(uint4*)(youth + grow*32 + cg*4) = hv;
                int yr = tl*KP + kk;
                *(float4*)(ysm + yr*YW + cg*8)     = make_float4(o[0], o[1], o[2], o[3]);
                *(float4*)(ysm + yr*YW + cg*8 + 4) = make_float4(o[4], o[5], o[6], o[7]);
            }
        }
    }
    __syncthreads();

    // ---- fused premix: layer-1 A = adj * y0 (packed, fixed-4 unroll, fp16) ----
    const size_t bnk = ((size_t)b*PADROWS + PAD + (size_t)t0*KP);
    for (int u = tid; u < 272*16; u += 288) {
        int row = u >> 4, p = u & 15;
        int c2 = c2base(p);
        int tl = row / KP, kk = row - tl*KP;
        const float* yb = ysm + tl*KP*YW + 2*c2;
        ull accA = 0ull, accB = 0ull;
        #pragma unroll
        for (int i = 0; i < 4; i++) {
            float wv = svw[kk*17 + i];
            ull wd = pack2(wv, wv);
            const float* yr = yb + svix[kk*17 + i]*YW;
            fma2(accA, wd, *(const ull*)yr);
            fma2(accB, wd, *(const ull*)(yr + 8));
        }
        float2 a = unpack2(accA), c = unpack2(accB);
        size_t pr = bnk + row;
        int pos = wpos(c2);
        *(uint2*)(g_xa0 + pr*32 + pos) = make_uint2(f16pack(a.x, a.y), f16pack(c.x, c.y));
    }
}

// ---------------------------------------------------------------------------
// finalize: pool = Σ(g_part + g_part1) -> LayerNorm -> FC
// ---------------------------------------------------------------------------
__global__ void finalize_kernel(const float* __restrict__ lns, const float* __restrict__ lnb,
                                const float* __restrict__ fcw, const float* __restrict__ fcb,
                                float* __restrict__ out)
{
    int b = blockIdx.x;
    int c = threadIdx.x;
    float s = 0.f;
    const float* pp = g_part  + (size_t)b * TILES_PB * 64;
    const float* pq = g_part1 + (size_t)b * TILES_PB * 64;
    for (int t = 0; t < TILES_PB; t++) s += pp[t*64 + c] + pq[t*64 + c];
    s *= (1.f / ((float)T_LEN * (float)KP));

    __shared__ float red[64];
    __shared__ float sf[64];
    red[c] = s; __syncthreads();
    for (int off = 32; off; off >>= 1) { if (c < off) red[c] += red[c+off]; __syncthreads(); }
    float mu = red[0] * (1.f/64.f);
    __syncthreads();
    float d = s - mu;
    red[c] = d * d; __syncthreads();
    for (int off = 32; off; off >>= 1) { if (c < off) red[c] += red[c+off]; __syncthreads(); }
    float var = red[0] * (1.f/64.f);
    float f = d * rsqrtf(var + 1e-5f) * lns[c] + lnb[c];
    sf[c] = f; __syncthreads();
    if (c < NCLS) {
        float o = fcb[c];
        #pragma unroll
        for (int i = 0; i < 64; i++) o += sf[i] * fcw[i*NCLS + c];
        out[b*NCLS + c] = o;
    }
}

extern "C" void kernel_launch(void* const* d_in, const int* in_sizes, int n_in,
                              void* d_out, int out_size)
{
    const float* kpts = (const float*)d_in[0];
    const float* adj  = (const float*)d_in[1];
    const float* gw0  = (const float*)d_in[2];
    const float* gw1  = (const float*)d_in[3];
    const float* gw2  = (const float*)d_in[4];
    const float* tcn  = (const float*)d_in[5];
    const float* bs   = (const float*)d_in[6];
    const float* bb   = (const float*)d_in[7];
    const float* bm   = (const float*)d_in[8];
    const float* bv   = (const float*)d_in[9];
    const float* lns  = (const float*)d_in[10];
    const float* lnb  = (const float*)d_in[11];
    const float* fcw  = (const float*)d_in[12];
    const float* fcb  = (const float*)d_in[13];
    float* out = (float*)d_out;

    float *buf1;
    uint32_t *y0h, *xa0, *xa1;
    cudaGetSymbolAddress((void**)&y0h, g_y0h);
    cudaGetSymbolAddress((void**)&buf1, g_buf1);
    cudaGetSymbolAddress((void**)&xa0, g_xa0);
    cudaGetSymbolAddress((void**)&xa1, g_xa1);

    int NTT = TILE_T + 2, XW = NTT*KPAD + 2;
    size_t s0 = (size_t)(272*YW + ((3*XW + 3) & ~3) + 3*3*HID + 308 + 64
                         + 289 + 289 + 20) * sizeof(float);
    cudaFuncSetAttribute(stblock0, cudaFuncAttributeMaxDynamicSharedMemorySize, (int)s0);
    cudaFuncSetAttribute(mma_kernel<17,false,true>, cudaFuncAttributeMaxDynamicSharedMemorySize, SMEM_MMA);
    cudaFuncSetAttribute(mma_kernel<34,true,false>, cudaFuncAttributeMaxDynamicSharedMemorySize, SMEM_MMA);

    prep_kernel<<<dim3(3,3), 64>>>(adj, gw0, gw1, gw2, tcn, bs, bb, bm, bv);
    zero_pads<<<dim3(32,16), 256>>>();

    dim3 grid0(NT, B_SZ);
    stblock0<<<grid0, 288, s0>>>(kpts, y0h, adj);

    mma_kernel<17,false,true><<<NTILES, 128, SMEM_MMA>>>(y0h, buf1, xa0, xa1, 0, 1);

    clean_premix<<<dim3(TILES_PB-1, B_SZ), 288>>>(buf1);

    mma_kernel<34,true,false><<<NTILES, 128, SMEM_MMA>>>(nullptr, nullptr, xa1, nullptr, 1, 2);

    finalize_kernel<<<B_SZ, 64>>>(lns, lnb, fcw, fcb, out);
}